// round 4
// baseline (speedup 1.0000x reference)
#include <cuda_runtime.h>
#include <cstdint>

// SimpleZoneODE: GCN layers are dead code (output unused by returned velocity).
// Effective computation:
//   time_vec = relu(t @ Wt1 + bt1) @ Wt2 + bt2                     [16]
//   c1       = bd1 + person @ Wd1[32:40] + time_vec @ Wd1[40:56]   [64]
//   per row: h1 = relu(ze @ Wd1[0:32] + c1); h2 = relu(h1@Wd2+bd2);
//            out = h2 @ Wd3 + bd3
// R2 design (resubmit #2 after infra timeouts): 1 row/thread, 128-thread
// blocks, launch_bounds(128,4) for 16 warps/SM; LDS.128 weight loads keep
// LDS:FFMA2 at the co-saturating 1:2 ratio; all math via packed fma.rn.f32x2.

typedef unsigned long long ull;

__device__ __align__(16) float g_c1[64];

static __device__ __forceinline__ ull fma2(ull a, ull b, ull c) {
    ull d;
    asm("fma.rn.f32x2 %0, %1, %2, %3;" : "=l"(d) : "l"(a), "l"(b), "l"(c));
    return d;
}
static __device__ __forceinline__ ull pack2(float x, float y) {
    ull r;
    asm("mov.b64 %0, {%1, %2};" : "=l"(r) : "f"(x), "f"(y));
    return r;
}
static __device__ __forceinline__ float2 unpack2(ull v) {
    float2 r;
    asm("mov.b64 {%0, %1}, %2;" : "=f"(r.x), "=f"(r.y) : "l"(v));
    return r;
}

// ---------------------------------------------------------------------------
// Prep: c1[64] = bd1 + person @ Wd1[32:40] + time_vec(t) @ Wd1[40:56].
// One block, 64 threads; thread j computes c1[j].
// ---------------------------------------------------------------------------
__global__ void prep_kernel(const float* __restrict__ t,
                            const float* __restrict__ person,
                            const float* __restrict__ Wt1,
                            const float* __restrict__ bt1,
                            const float* __restrict__ Wt2,
                            const float* __restrict__ bt2,
                            const float* __restrict__ Wd1,
                            const float* __restrict__ bd1)
{
    const int j = threadIdx.x;  // 0..63
    const float tt = t[0];
    float hid[16];
#pragma unroll
    for (int i = 0; i < 16; i++)
        hid[i] = fmaxf(fmaf(tt, Wt1[i], bt1[i]), 0.f);

    float s = bd1[j];
#pragma unroll
    for (int ii = 0; ii < 16; ii++) {
        float tv = bt2[ii];
#pragma unroll
        for (int i = 0; i < 16; i++)
            tv = fmaf(hid[i], Wt2[i * 16 + ii], tv);
        s = fmaf(tv, Wd1[(40 + ii) * 64 + j], s);
    }
#pragma unroll
    for (int p = 0; p < 8; p++)
        s = fmaf(person[p], Wd1[(32 + p) * 64 + j], s);

    g_c1[j] = s;
}

// ---------------------------------------------------------------------------
// Fused 3-layer MLP. 128 threads/block, 1 row/thread.
// ---------------------------------------------------------------------------
__global__ __launch_bounds__(128, 4) void zone_mlp_kernel(
    const float* __restrict__ ze,     // [n,32]
    const float* __restrict__ Wd1,    // [56,64] (rows 0..31 used here)
    const float* __restrict__ Wd2,    // [64,32]
    const float* __restrict__ bd2,    // [32]
    const float* __restrict__ Wd3,    // [32,32]
    const float* __restrict__ bd3,    // [32]
    float* __restrict__ out,          // [n,32]
    int n)
{
    __shared__ __align__(16) ull sW1[32 * 32];  // [k][colpair]
    __shared__ __align__(16) ull sW2[64 * 16];
    __shared__ __align__(16) ull sW3[32 * 16];
    __shared__ __align__(16) ull sC1[32];
    __shared__ __align__(16) ull sB2[16];
    __shared__ __align__(16) ull sB3[16];

    const int tid = threadIdx.x;
    {
        const ull* gA  = (const ull*)Wd1;   // first 2048 floats = rows 0..31
        const ull* gW2 = (const ull*)Wd2;
        const ull* gW3 = (const ull*)Wd3;
#pragma unroll
        for (int i = 0; i < 8; i++) {
            sW1[tid + 128 * i] = gA[tid + 128 * i];
            sW2[tid + 128 * i] = gW2[tid + 128 * i];
        }
#pragma unroll
        for (int i = 0; i < 4; i++)
            sW3[tid + 128 * i] = gW3[tid + 128 * i];
        if (tid < 32) sC1[tid] = ((const ull*)g_c1)[tid];
        if (tid < 16) { sB2[tid] = ((const ull*)bd2)[tid]; sB3[tid] = ((const ull*)bd3)[tid]; }
    }
    __syncthreads();

    const int r = blockIdx.x * 128 + tid;
    const bool v = (r < n);

    // Load embedding row (coalesced float4).
    float zr[32];
#pragma unroll
    for (int q = 0; q < 8; q++) {
        float4 a = make_float4(0.f, 0.f, 0.f, 0.f);
        if (v) a = ((const float4*)(ze + (size_t)r * 32))[q];
        zr[4*q+0] = a.x; zr[4*q+1] = a.y; zr[4*q+2] = a.z; zr[4*q+3] = a.w;
    }

    // ---- Layer 1: a[64 cols as 32 pairs] = ze @ Wd1[0:32] + c1 ----
    ull a[32];
#pragma unroll
    for (int jp = 0; jp < 32; jp++) a[jp] = sC1[jp];

#pragma unroll
    for (int k = 0; k < 32; k++) {
        const ull s = pack2(zr[k], zr[k]);
        const ulonglong2* wrow = (const ulonglong2*)(sW1 + k * 32);
#pragma unroll
        for (int q = 0; q < 16; q++) {
            const ulonglong2 w = wrow[q];
            a[2*q]     = fma2(s, w.x, a[2*q]);
            a[2*q + 1] = fma2(s, w.y, a[2*q + 1]);
        }
    }

    // ---- Layer 2: h2[32 cols as 16 pairs] = relu(a) @ Wd2 + bd2 ----
    ull h2[16];
#pragma unroll
    for (int jp = 0; jp < 16; jp++) h2[jp] = sB2[jp];

#pragma unroll
    for (int kp = 0; kp < 32; kp++) {
        const float2 p = unpack2(a[kp]);
        const ull s0 = pack2(fmaxf(p.x, 0.f), fmaxf(p.x, 0.f));
        const ull s1 = pack2(fmaxf(p.y, 0.f), fmaxf(p.y, 0.f));
        const ulonglong2* w0r = (const ulonglong2*)(sW2 + (2 * kp) * 16);
        const ulonglong2* w1r = (const ulonglong2*)(sW2 + (2 * kp + 1) * 16);
#pragma unroll
        for (int q = 0; q < 8; q++) {
            const ulonglong2 w0 = w0r[q];
            const ulonglong2 w1 = w1r[q];
            h2[2*q]     = fma2(s0, w0.x, h2[2*q]);
            h2[2*q + 1] = fma2(s0, w0.y, h2[2*q + 1]);
            h2[2*q]     = fma2(s1, w1.x, h2[2*q]);
            h2[2*q + 1] = fma2(s1, w1.y, h2[2*q + 1]);
        }
    }

    // ---- Layer 3: o[32 cols as 16 pairs] = relu(h2) @ Wd3 + bd3 ----
    ull o[16];
#pragma unroll
    for (int jp = 0; jp < 16; jp++) o[jp] = sB3[jp];

#pragma unroll
    for (int kp = 0; kp < 16; kp++) {
        const float2 p = unpack2(h2[kp]);
        const ull s0 = pack2(fmaxf(p.x, 0.f), fmaxf(p.x, 0.f));
        const ull s1 = pack2(fmaxf(p.y, 0.f), fmaxf(p.y, 0.f));
        const ulonglong2* w0r = (const ulonglong2*)(sW3 + (2 * kp) * 16);
        const ulonglong2* w1r = (const ulonglong2*)(sW3 + (2 * kp + 1) * 16);
#pragma unroll
        for (int q = 0; q < 8; q++) {
            const ulonglong2 w0 = w0r[q];
            const ulonglong2 w1 = w1r[q];
            o[2*q]     = fma2(s0, w0.x, o[2*q]);
            o[2*q + 1] = fma2(s0, w0.y, o[2*q + 1]);
            o[2*q]     = fma2(s1, w1.x, o[2*q]);
            o[2*q + 1] = fma2(s1, w1.y, o[2*q + 1]);
        }
    }

    if (v) {
        ulonglong2* p = (ulonglong2*)(out + (size_t)r * 32);
#pragma unroll
        for (int q = 0; q < 8; q++)
            p[q] = make_ulonglong2(o[2 * q], o[2 * q + 1]);
    }
}

// ---------------------------------------------------------------------------
// Inputs: 0 t, 1 zone_embedding, 2 zone_features, 3 person_attrs,
// 4 edge_index, 5 W1, 6 b1, 7 W2, 8 b2, 9 Wt1, 10 bt1, 11 Wt2, 12 bt2,
// 13 Wd1, 14 bd1, 15 Wd2, 16 bd2, 17 Wd3, 18 bd3.  Output [n,32] f32.
// ---------------------------------------------------------------------------
extern "C" void kernel_launch(void* const* d_in, const int* in_sizes, int n_in,
                              void* d_out, int out_size)
{
    const float* t      = (const float*)d_in[0];
    const float* ze     = (const float*)d_in[1];
    const float* person = (const float*)d_in[3];
    const float* Wt1    = (const float*)d_in[9];
    const float* bt1    = (const float*)d_in[10];
    const float* Wt2    = (const float*)d_in[11];
    const float* bt2    = (const float*)d_in[12];
    const float* Wd1    = (const float*)d_in[13];
    const float* bd1    = (const float*)d_in[14];
    const float* Wd2    = (const float*)d_in[15];
    const float* bd2    = (const float*)d_in[16];
    const float* Wd3    = (const float*)d_in[17];
    const float* bd3    = (const float*)d_in[18];
    float* out = (float*)d_out;

    const int n = in_sizes[1] / 32;

    prep_kernel<<<1, 64>>>(t, person, Wt1, bt1, Wt2, bt2, Wd1, bd1);

    const int blocks = (n + 127) / 128;
    zone_mlp_kernel<<<blocks, 128>>>(ze, Wd1, Wd2, bd2, Wd3, bd3, out, n);
}